// round 11
// baseline (speedup 1.0000x reference)
#include <cuda_runtime.h>
#include <cuda_fp16.h>
#include <cstdint>

// ============================================================================
// out = LayerNorm(relu(x @ (m*W_v + (1-m)*W_r)))   [attention path is identity:
// softmax rows sum to 1 and the reference einsum contracts the softmax axis]
//   x: [131072, 256] f32,  W: [256, 512] f32,  out: [131072, 512] f32
// R11: MAX-BURST inner loop. KC=32 so ALL fragments of a chunk fit in regs
// (8 A-ldsm4 + 8 B-ldsm4), then 64 HMMAs fire with no intervening shared
// loads (tensor-idle gaps amortized once per chunk). 4-stage A/B rings,
// barrier on even chunks only. fp16 mma.sync, 8 warps, warp = 64x64.
// ============================================================================

static constexpr int K_DIM = 256;
static constexpr int N_DIM = 512;
static constexpr int BM    = 64;
static constexpr int KC    = 32;
static constexpr int NCH   = K_DIM / KC;   // 8
static constexpr int M_TOT = 2048 * 64;    // 131072
static constexpr int NT    = 256;          // 8 warps; warp = 64 rows x 64 cols

// SMEM layout (bytes)
static constexpr int SM_B  = 0;            // 4 stages x 32768 (packed 2 n-rows / 128B)
static constexpr int SM_A  = 131072;       // 4 stages x 8192 (64 rows x 128B, 64B used)
static constexpr int SM_GB = 163840;       // gamma[512]+beta[512] f32 = 4 KB
static constexpr int SM_PS = 167936;       // psum[64][8]+psq[64][8]+stats[64][2] = 4608
static constexpr int SMEM_TOTAL = 172544;

// Pre-swizzled fp16 B chunk images (exact smem stage byte layout):
// off(n, kk) = swz((n>>1)*128 + (n&1)*64 + kk*2), kk = k % 32, chunk = k / 32.
__device__ __align__(16) unsigned char g_Bimg[NCH][32768];

// ---------------------------------------------------------------------------
__device__ __forceinline__ uint32_t smem_u32(const void* p) {
    uint32_t r;
    asm("{ .reg .u64 t; cvta.to.shared.u64 t, %1; cvt.u32.u64 %0, t; }" : "=r"(r) : "l"(p));
    return r;
}
__host__ __device__ __forceinline__ uint32_t swz(uint32_t o) { return o ^ ((o >> 3) & 0x70); }

__device__ __forceinline__ void cp16(uint32_t d, const void* s) {
    asm volatile("cp.async.cg.shared.global [%0], [%1], 16;" :: "r"(d), "l"(s));
}
__device__ __forceinline__ void cp_commit() { asm volatile("cp.async.commit_group;"); }
__device__ __forceinline__ void cp_wait0()  { asm volatile("cp.async.wait_group 0;"); }

__device__ __forceinline__ void ldsm4(uint32_t* r, uint32_t a) {
    asm volatile("ldmatrix.sync.aligned.m8n8.x4.shared.b16 {%0,%1,%2,%3}, [%4];"
                 : "=r"(r[0]), "=r"(r[1]), "=r"(r[2]), "=r"(r[3]) : "r"(a));
}
__device__ __forceinline__ void hmma(float* c, const uint32_t* a, const uint32_t* b) {
    asm volatile("mma.sync.aligned.m16n8k16.row.col.f32.f16.f16.f32 "
                 "{%0,%1,%2,%3},{%4,%5,%6,%7},{%8,%9},{%0,%1,%2,%3};"
                 : "+f"(c[0]), "+f"(c[1]), "+f"(c[2]), "+f"(c[3])
                 : "r"(a[0]), "r"(a[1]), "r"(a[2]), "r"(a[3]), "r"(b[0]), "r"(b[1]));
}

// ---------------------------------------------------------------------------
// Prep: W_c = m*W_v + (1-m)*W_r -> fp16, pre-swizzled packed chunk images.
// ---------------------------------------------------------------------------
__global__ void prep_kernel(const float* __restrict__ Wv, const float* __restrict__ Wr,
                            const float* __restrict__ mix) {
    int gid = blockIdx.x * blockDim.x + threadIdx.x;
    if (gid >= K_DIM * N_DIM) return;
    int n = gid & 511;
    int k = gid >> 9;
    float m = 1.0f / (1.0f + expf(-mix[0]));
    float w = m * Wv[k * N_DIM + n] + (1.0f - m) * Wr[k * N_DIM + n];
    int c  = k >> 5;
    int kk = k & 31;
    uint32_t off = swz((uint32_t)((n >> 1) * 128 + (n & 1) * 64 + kk * 2));
    *(__half*)(&g_Bimg[c][off]) = __float2half(w);
}

// ---------------------------------------------------------------------------
// Fused GEMM (fp16 mma.sync, max-burst) + relu + LayerNorm(512)
// ---------------------------------------------------------------------------
__global__ void __launch_bounds__(NT, 1)
gemm_ln_kernel(const float* __restrict__ x, const float* __restrict__ gamma,
               const float* __restrict__ beta, float* __restrict__ out) {
    extern __shared__ char smem[];
    const uint32_t sb = smem_u32(smem);
    const int tid  = threadIdx.x;
    const int wn   = tid >> 5;    // warp 0..7 -> 64-col slice, all 64 rows
    const int lane = tid & 31;

    const size_t m0 = (size_t)blockIdx.x * BM;

    // gamma/beta into smem
    {
        float* gsh = (float*)(smem + SM_GB);
        for (int i = tid; i < N_DIM; i += NT) {
            gsh[i]         = gamma[i];
            gsh[N_DIM + i] = beta[i];
        }
    }

    // ldmatrix base offsets
    const uint32_t arow = (uint32_t)((lane & 15) * 128 + (lane >> 4) * 16);   // + mt*2048 + ks*32
    const int nb = wn * 64 + ((lane >> 4) & 1) * 8 + (lane & 7);
    const uint32_t brow = (uint32_t)((nb >> 1) * 128 + (nb & 1) * 64 + ((lane >> 3) & 1) * 16); // + bt*1024 + ks*32

    float acc[4][8][4];
    #pragma unroll
    for (int mt = 0; mt < 4; mt++)
        #pragma unroll
        for (int nt = 0; nt < 8; nt++)
            #pragma unroll
            for (int i = 0; i < 4; i++) acc[mt][nt][i] = 0.0f;

    // A indexing: chunk = 64 rows x 32 f32 = 512 float4; 2 per thread
    int arowi[2], asegi[2];
    uint32_t asoff[2];
    #pragma unroll
    for (int i = 0; i < 2; i++) {
        int idx = tid + i * NT;            // 0..511
        arowi[i] = idx >> 3;               // 0..63
        asegi[i] = (idx & 7) * 4;          // float offset in chunk
        asoff[i] = swz((uint32_t)((idx >> 3) * 128 + (idx & 7) * 8));
    }

    // ---- prologue: B chunks 0,1 via cp.async; A chunks 0,1 STS; A chunk2 regs ----
    #pragma unroll
    for (int s = 0; s < 2; s++) {
        #pragma unroll
        for (int i = 0; i < 8; i++) {
            int j = tid + i * NT;          // 0..2047
            cp16(sb + SM_B + s * 32768 + j * 16, &g_Bimg[s][j * 16]);
        }
        cp_commit();
    }
    float4 av[2];
    #pragma unroll
    for (int s = 0; s < 2; s++) {
        #pragma unroll
        for (int i = 0; i < 2; i++)
            av[i] = *(const float4*)(x + (m0 + arowi[i]) * K_DIM + s * KC + asegi[i]);
        #pragma unroll
        for (int i = 0; i < 2; i++) {
            __half2 h01 = __floats2half2_rn(av[i].x, av[i].y);
            __half2 h23 = __floats2half2_rn(av[i].z, av[i].w);
            *(uint2*)(smem + SM_A + s * 8192 + asoff[i]) =
                make_uint2(*(uint32_t*)&h01, *(uint32_t*)&h23);
        }
    }
    #pragma unroll
    for (int i = 0; i < 2; i++)
        av[i] = *(const float4*)(x + (m0 + arowi[i]) * K_DIM + 2 * KC + asegi[i]);

    // ---- main loop: barrier on even chunks only (write distance 2) ----
    #pragma unroll
    for (int c = 0; c < NCH; c++) {
        if ((c & 1) == 0) {
            cp_wait0();
            __syncthreads();
        }

        // prefetch for chunk c+2 (stage (c+2)&3)
        if (c + 2 < NCH) {
            const int pst = (c + 2) & 3;
            // STS A chunk c+2 from regs
            #pragma unroll
            for (int i = 0; i < 2; i++) {
                __half2 h01 = __floats2half2_rn(av[i].x, av[i].y);
                __half2 h23 = __floats2half2_rn(av[i].z, av[i].w);
                *(uint2*)(smem + SM_A + pst * 8192 + asoff[i]) =
                    make_uint2(*(uint32_t*)&h01, *(uint32_t*)&h23);
            }
            // LDG A chunk c+3
            if (c + 3 < NCH)
                #pragma unroll
                for (int i = 0; i < 2; i++)
                    av[i] = *(const float4*)(x + (m0 + arowi[i]) * K_DIM
                                             + (c + 3) * KC + asegi[i]);
        }

        // ---- fragment preload: ALL chunk fragments -> regs (one ldsm batch) ----
        const uint32_t Ab = sb + SM_A + (c & 3) * 8192;
        const uint32_t Bb = sb + SM_B + (c & 3) * 32768;
        uint32_t af[2][4][4];   // [ks][mt]
        uint32_t bfr[2][4][4];  // [ks][bt] (two n8k16 frags each)
        #pragma unroll
        for (int ks = 0; ks < 2; ks++)
            #pragma unroll
            for (int mt = 0; mt < 4; mt++)
                ldsm4(af[ks][mt], Ab + swz(arow + mt * 2048 + ks * 32));
        #pragma unroll
        for (int ks = 0; ks < 2; ks++)
            #pragma unroll
            for (int bt = 0; bt < 4; bt++)
                ldsm4(bfr[ks][bt], Bb + swz(brow + bt * 1024 + ks * 32));

        // B cp.async for chunk c+2 in the ldsm latency shadow
        if (c + 2 < NCH) {
            const int pst = (c + 2) & 3;
            #pragma unroll
            for (int i = 0; i < 8; i++) {
                int j = tid + i * NT;
                cp16(sb + SM_B + pst * 32768 + j * 16, &g_Bimg[c + 2][j * 16]);
            }
        }
        cp_commit();

        // ---- 64-HMMA uninterrupted burst ----
        #pragma unroll
        for (int ks = 0; ks < 2; ks++)
            #pragma unroll
            for (int bt = 0; bt < 4; bt++)
                #pragma unroll
                for (int mt = 0; mt < 4; mt++) {
                    hmma(acc[mt][2 * bt],     af[ks][mt], &bfr[ks][bt][0]);
                    hmma(acc[mt][2 * bt + 1], af[ks][mt], &bfr[ks][bt][2]);
                }
    }

    // ------------------- Epilogue: relu + LayerNorm(512) -------------------
    float* psum  = (float*)(smem + SM_PS);   // [64][8]
    float* psq   = psum + 512;               // [64][8]
    float* stats = psq + 512;                // [64][2]

    #pragma unroll
    for (int mt = 0; mt < 4; mt++) {
        #pragma unroll
        for (int half = 0; half < 2; half++) {
            float s = 0.0f, q = 0.0f;
            #pragma unroll
            for (int nt = 0; nt < 8; nt++) {
                float v0 = fmaxf(acc[mt][nt][half * 2 + 0], 0.0f);
                float v1 = fmaxf(acc[mt][nt][half * 2 + 1], 0.0f);
                s += v0 + v1;
                q += v0 * v0 + v1 * v1;
            }
            s += __shfl_xor_sync(0xFFFFFFFFu, s, 1);
            q += __shfl_xor_sync(0xFFFFFFFFu, q, 1);
            s += __shfl_xor_sync(0xFFFFFFFFu, s, 2);
            q += __shfl_xor_sync(0xFFFFFFFFu, q, 2);
            if ((lane & 3) == 0) {
                int r = mt * 16 + (lane >> 2) + half * 8;   // 0..63
                psum[r * 8 + wn] = s;
                psq[r * 8 + wn]  = q;
            }
        }
    }
    __syncthreads();
    if (tid < BM) {
        float st = 0.0f, qt = 0.0f;
        #pragma unroll
        for (int i = 0; i < 8; i++) { st += psum[tid * 8 + i]; qt += psq[tid * 8 + i]; }
        float mean = st * (1.0f / 512.0f);
        float var  = qt * (1.0f / 512.0f) - mean * mean;
        stats[tid * 2]     = mean;
        stats[tid * 2 + 1] = rsqrtf(var + 1e-5f);
    }
    __syncthreads();

    const float* gsh = (const float*)(smem + SM_GB);
    const float* bsh = gsh + N_DIM;
    #pragma unroll
    for (int mt = 0; mt < 4; mt++) {
        #pragma unroll
        for (int half = 0; half < 2; half++) {
            int r = mt * 16 + (lane >> 2) + half * 8;
            float mean = stats[r * 2];
            float rstd = stats[r * 2 + 1];
            float* orow = out + (size_t)(m0 + r) * N_DIM;
            #pragma unroll
            for (int nt = 0; nt < 8; nt++) {
                int col = wn * 64 + nt * 8 + (lane & 3) * 2;
                float2 o;
                o.x = (fmaxf(acc[mt][nt][half * 2 + 0], 0.0f) - mean) * rstd * gsh[col]     + bsh[col];
                o.y = (fmaxf(acc[mt][nt][half * 2 + 1], 0.0f) - mean) * rstd * gsh[col + 1] + bsh[col + 1];
                *(float2*)(orow + col) = o;
            }
        }
    }
}

// ---------------------------------------------------------------------------
// Host launcher. Inputs: x, W_q, W_k, W_v, W_r, mix, gamma, beta
// ---------------------------------------------------------------------------
extern "C" void kernel_launch(void* const* d_in, const int* in_sizes, int n_in,
                              void* d_out, int out_size) {
    const float* x     = (const float*)d_in[0];
    const float* Wv    = (const float*)d_in[3];
    const float* Wr    = (const float*)d_in[4];
    const float* mix   = (const float*)d_in[5];
    const float* gamma = (const float*)d_in[6];
    const float* beta  = (const float*)d_in[7];
    float* out = (float*)d_out;

    cudaFuncSetAttribute(gemm_ln_kernel, cudaFuncAttributeMaxDynamicSharedMemorySize, SMEM_TOTAL);

    prep_kernel<<<(K_DIM * N_DIM + 255) / 256, 256>>>(Wv, Wr, mix);
    gemm_ln_kernel<<<M_TOT / BM, NT, SMEM_TOTAL>>>(x, gamma, beta, out);
}

// round 12
// speedup vs baseline: 1.1169x; 1.1169x over previous
#include <cuda_runtime.h>
#include <cuda_fp16.h>
#include <cstdint>

// ============================================================================
// out = LayerNorm(relu(x @ (m*W_v + (1-m)*W_r)))   [attention path is identity:
// softmax rows sum to 1 and the reference einsum contracts the softmax axis]
//   x: [131072, 256] f32,  W: [256, 512] f32,  out: [131072, 512] f32
// R12: WARP-ROLE SPECIALIZATION. Warps 0-3 (one per SMSP) do all loading
// (LDG/STS A, cp.async B, commit/wait) plus their own MMA slice; warps 4-7
// do MMA only. On every SMSP the pure-MMA warp keeps the tensor pipe busy
// while the loader warp issues loads -> breaks the lockstep [load][mma]
// phase structure that has pinned tensor% at ~37% for seven rounds.
// fp16 mma.sync, 64x64 warp tiles, KC=64 double-buffered, NT=256.
// ============================================================================

static constexpr int K_DIM = 256;
static constexpr int N_DIM = 512;
static constexpr int BM    = 64;
static constexpr int KC    = 64;
static constexpr int NCH   = K_DIM / KC;   // 4
static constexpr int M_TOT = 2048 * 64;    // 131072
static constexpr int NT    = 256;          // 8 warps; warp = 64 rows x 64 cols

// SMEM layout (bytes)
static constexpr int SM_B  = 0;            // 2 stages x 64 KB (512 n-rows x 128B)
static constexpr int SM_A  = 131072;       // 2 stages x 8 KB (64 rows x 128B)
static constexpr int SM_GB = 147456;       // gamma[512]+beta[512] f32 = 4 KB
static constexpr int SM_PS = 151552;       // psum[64][8]+psq[64][8]+stats[64][2]
static constexpr int SMEM_TOTAL = 156160;

// Pre-swizzled fp16 B chunk images: off(n,kk) = swz(n*128 + kk*2), kk = k%64.
__device__ __align__(16) unsigned char g_Bimg[NCH][65536];

// ---------------------------------------------------------------------------
__device__ __forceinline__ uint32_t smem_u32(const void* p) {
    uint32_t r;
    asm("{ .reg .u64 t; cvta.to.shared.u64 t, %1; cvt.u32.u64 %0, t; }" : "=r"(r) : "l"(p));
    return r;
}
__host__ __device__ __forceinline__ uint32_t swz(uint32_t o) { return o ^ ((o >> 3) & 0x70); }

__device__ __forceinline__ void cp16(uint32_t d, const void* s) {
    asm volatile("cp.async.cg.shared.global [%0], [%1], 16;" :: "r"(d), "l"(s));
}
__device__ __forceinline__ void cp_commit() { asm volatile("cp.async.commit_group;"); }
__device__ __forceinline__ void cp_wait0()  { asm volatile("cp.async.wait_group 0;"); }

__device__ __forceinline__ void ldsm4(uint32_t* r, uint32_t a) {
    asm volatile("ldmatrix.sync.aligned.m8n8.x4.shared.b16 {%0,%1,%2,%3}, [%4];"
                 : "=r"(r[0]), "=r"(r[1]), "=r"(r[2]), "=r"(r[3]) : "r"(a));
}
__device__ __forceinline__ void hmma(float* c, const uint32_t* a, const uint32_t* b) {
    asm volatile("mma.sync.aligned.m16n8k16.row.col.f32.f16.f16.f32 "
                 "{%0,%1,%2,%3},{%4,%5,%6,%7},{%8,%9},{%0,%1,%2,%3};"
                 : "+f"(c[0]), "+f"(c[1]), "+f"(c[2]), "+f"(c[3])
                 : "r"(a[0]), "r"(a[1]), "r"(a[2]), "r"(a[3]), "r"(b[0]), "r"(b[1]));
}

// ---------------------------------------------------------------------------
// Prep: W_c = m*W_v + (1-m)*W_r -> fp16, pre-swizzled chunk images.
// ---------------------------------------------------------------------------
__global__ void prep_kernel(const float* __restrict__ Wv, const float* __restrict__ Wr,
                            const float* __restrict__ mix) {
    int gid = blockIdx.x * blockDim.x + threadIdx.x;
    if (gid >= K_DIM * N_DIM) return;
    int n = gid & 511;
    int k = gid >> 9;
    float m = 1.0f / (1.0f + expf(-mix[0]));
    float w = m * Wv[k * N_DIM + n] + (1.0f - m) * Wr[k * N_DIM + n];
    int c  = k >> 6;
    int kk = k & 63;
    uint32_t off = swz((uint32_t)(n * 128 + kk * 2));
    *(__half*)(&g_Bimg[c][off]) = __float2half(w);
}

// ---------------------------------------------------------------------------
// Fused GEMM (fp16 mma.sync, warp-role specialized) + relu + LayerNorm(512)
// ---------------------------------------------------------------------------
__global__ void __launch_bounds__(NT, 1)
gemm_ln_kernel(const float* __restrict__ x, const float* __restrict__ gamma,
               const float* __restrict__ beta, float* __restrict__ out) {
    extern __shared__ char smem[];
    const uint32_t sb = smem_u32(smem);
    const int tid  = threadIdx.x;
    const int wn   = tid >> 5;    // warp 0..7 -> 64-col slice, all 64 rows
    const int lane = tid & 31;
    const bool loader = (wn < 4); // warps 0-3: one loader per SMSP

    const size_t m0 = (size_t)blockIdx.x * BM;

    // gamma/beta into smem
    {
        float* gsh = (float*)(smem + SM_GB);
        for (int i = tid; i < N_DIM; i += NT) {
            gsh[i]         = gamma[i];
            gsh[N_DIM + i] = beta[i];
        }
    }

    // ldmatrix base offsets
    const uint32_t arow = (uint32_t)((lane & 15) * 128 + (lane >> 4) * 16);   // + mt*2048 + ks*32
    const uint32_t brow = (uint32_t)((wn * 64 + ((lane >> 4) & 1) * 8 + (lane & 7)) * 128
                                     + ((lane >> 3) & 1) * 16);               // + bt*2048 + ks*32

    float acc[4][8][4];
    #pragma unroll
    for (int mt = 0; mt < 4; mt++)
        #pragma unroll
        for (int nt = 0; nt < 8; nt++)
            #pragma unroll
            for (int i = 0; i < 4; i++) acc[mt][nt][i] = 0.0f;

    // Loader-warp A indexing: 1024 float4 per chunk over 128 threads -> 8 each
    int arowi[8], asegi[8];
    uint32_t asoff[8];
    #pragma unroll
    for (int i = 0; i < 8; i++) {
        int idx = tid + i * 128;           // 0..1023 (loader threads: tid<128)
        arowi[i] = idx >> 4;
        asegi[i] = (idx & 15) * 4;
        asoff[i] = swz((uint32_t)((idx >> 4) * 128 + (idx & 15) * 8));
    }

    float4 av[8];
    // ---- prologue (loader warps only): B0 cp.async; A0 LDG+STS; A1 LDG ----
    if (loader) {
        #pragma unroll
        for (int i = 0; i < 32; i++) {
            int j = tid + i * 128;         // 0..4095
            cp16(sb + SM_B + j * 16, &g_Bimg[0][j * 16]);
        }
        cp_commit();
        #pragma unroll
        for (int i = 0; i < 8; i++)
            av[i] = *(const float4*)(x + (m0 + arowi[i]) * K_DIM + asegi[i]);
        #pragma unroll
        for (int i = 0; i < 8; i++) {
            __half2 h01 = __floats2half2_rn(av[i].x, av[i].y);
            __half2 h23 = __floats2half2_rn(av[i].z, av[i].w);
            *(uint2*)(smem + SM_A + asoff[i]) = make_uint2(*(uint32_t*)&h01, *(uint32_t*)&h23);
        }
        #pragma unroll
        for (int i = 0; i < 8; i++)
            av[i] = *(const float4*)(x + (m0 + arowi[i]) * K_DIM + KC + asegi[i]);
    }

    #pragma unroll
    for (int c = 0; c < NCH; c++) {
        const int buf = c & 1;
        if (loader) cp_wait0();            // drains B stage c (committed in region c-1)
        __syncthreads();                   // publish stage c to all warps

        // loader warps: produce stage c+1 (writes go to buf^1, last read 2 regions ago)
        if (loader && c < NCH - 1) {
            const int nbuf = buf ^ 1;
            #pragma unroll
            for (int i = 0; i < 8; i++) {
                __half2 h01 = __floats2half2_rn(av[i].x, av[i].y);
                __half2 h23 = __floats2half2_rn(av[i].z, av[i].w);
                *(uint2*)(smem + SM_A + nbuf * 8192 + asoff[i]) =
                    make_uint2(*(uint32_t*)&h01, *(uint32_t*)&h23);
            }
            if (c < NCH - 2) {
                #pragma unroll
                for (int i = 0; i < 8; i++)
                    av[i] = *(const float4*)(x + (m0 + arowi[i]) * K_DIM
                                             + (c + 2) * KC + asegi[i]);
            }
            #pragma unroll
            for (int i = 0; i < 32; i++) {
                int j = tid + i * 128;
                cp16(sb + SM_B + nbuf * 65536 + j * 16, &g_Bimg[c + 1][j * 16]);
            }
            cp_commit();
        }

        // ---- MMA chunk c (all warps; pure-MMA warps start here immediately) ----
        const uint32_t Ab = sb + SM_A + buf * 8192;
        const uint32_t Bb = sb + SM_B + buf * 65536;
        uint32_t af[2][4][4];
        #pragma unroll
        for (int mt = 0; mt < 4; mt++)
            ldsm4(af[0][mt], Ab + swz(arow + mt * 2048));
        #pragma unroll
        for (int ks = 0; ks < 4; ks++) {
            const int cur = ks & 1, nxt = cur ^ 1;
            if (ks < 3)
                #pragma unroll
                for (int mt = 0; mt < 4; mt++)
                    ldsm4(af[nxt][mt], Ab + swz(arow + mt * 2048 + (ks + 1) * 32));
            #pragma unroll
            for (int bt = 0; bt < 4; bt++) {
                uint32_t bh[4];
                ldsm4(bh, Bb + swz(brow + bt * 2048 + ks * 32));
                #pragma unroll
                for (int mt = 0; mt < 4; mt++) {
                    hmma(acc[mt][2 * bt],     af[cur][mt], &bh[0]);
                    hmma(acc[mt][2 * bt + 1], af[cur][mt], &bh[2]);
                }
            }
        }
        // no trailing barrier: next region's entry barrier orders buffer reuse
    }

    // ------------------- Epilogue: relu + LayerNorm(512) -------------------
    float* psum  = (float*)(smem + SM_PS);   // [64][8]
    float* psq   = psum + 512;               // [64][8]
    float* stats = psq + 512;                // [64][2]

    #pragma unroll
    for (int mt = 0; mt < 4; mt++) {
        #pragma unroll
        for (int half = 0; half < 2; half++) {
            float s = 0.0f, q = 0.0f;
            #pragma unroll
            for (int nt = 0; nt < 8; nt++) {
                float v0 = fmaxf(acc[mt][nt][half * 2 + 0], 0.0f);
                float v1 = fmaxf(acc[mt][nt][half * 2 + 1], 0.0f);
                s += v0 + v1;
                q += v0 * v0 + v1 * v1;
            }
            s += __shfl_xor_sync(0xFFFFFFFFu, s, 1);
            q += __shfl_xor_sync(0xFFFFFFFFu, q, 1);
            s += __shfl_xor_sync(0xFFFFFFFFu, s, 2);
            q += __shfl_xor_sync(0xFFFFFFFFu, q, 2);
            if ((lane & 3) == 0) {
                int r = mt * 16 + (lane >> 2) + half * 8;   // 0..63
                psum[r * 8 + wn] = s;
                psq[r * 8 + wn]  = q;
            }
        }
    }
    __syncthreads();
    if (tid < BM) {
        float st = 0.0f, qt = 0.0f;
        #pragma unroll
        for (int i = 0; i < 8; i++) { st += psum[tid * 8 + i]; qt += psq[tid * 8 + i]; }
        float mean = st * (1.0f / 512.0f);
        float var  = qt * (1.0f / 512.0f) - mean * mean;
        stats[tid * 2]     = mean;
        stats[tid * 2 + 1] = rsqrtf(var + 1e-5f);
    }
    __syncthreads();

    const float* gsh = (const float*)(smem + SM_GB);
    const float* bsh = gsh + N_DIM;
    #pragma unroll
    for (int mt = 0; mt < 4; mt++) {
        #pragma unroll
        for (int half = 0; half < 2; half++) {
            int r = mt * 16 + (lane >> 2) + half * 8;
            float mean = stats[r * 2];
            float rstd = stats[r * 2 + 1];
            float* orow = out + (size_t)(m0 + r) * N_DIM;
            #pragma unroll
            for (int nt = 0; nt < 8; nt++) {
                int col = wn * 64 + nt * 8 + (lane & 3) * 2;
                float2 o;
                o.x = (fmaxf(acc[mt][nt][half * 2 + 0], 0.0f) - mean) * rstd * gsh[col]     + bsh[col];
                o.y = (fmaxf(acc[mt][nt][half * 2 + 1], 0.0f) - mean) * rstd * gsh[col + 1] + bsh[col + 1];
                *(float2*)(orow + col) = o;
            }
        }
    }
}

// ---------------------------------------------------------------------------
// Host launcher. Inputs: x, W_q, W_k, W_v, W_r, mix, gamma, beta
// ---------------------------------------------------------------------------
extern "C" void kernel_launch(void* const* d_in, const int* in_sizes, int n_in,
                              void* d_out, int out_size) {
    const float* x     = (const float*)d_in[0];
    const float* Wv    = (const float*)d_in[3];
    const float* Wr    = (const float*)d_in[4];
    const float* mix   = (const float*)d_in[5];
    const float* gamma = (const float*)d_in[6];
    const float* beta  = (const float*)d_in[7];
    float* out = (float*)d_out;

    cudaFuncSetAttribute(gemm_ln_kernel, cudaFuncAttributeMaxDynamicSharedMemorySize, SMEM_TOTAL);

    prep_kernel<<<(K_DIM * N_DIM + 255) / 256, 256>>>(Wv, Wr, mix);
    gemm_ln_kernel<<<M_TOT / BM, NT, SMEM_TOTAL>>>(x, gamma, beta, out);
}

// round 13
// speedup vs baseline: 1.2800x; 1.1461x over previous
#include <cuda_runtime.h>
#include <cuda_fp16.h>
#include <cstdint>

// ============================================================================
// out = LayerNorm(relu(x @ (m*W_v + (1-m)*W_r)))   [attention path is identity:
// softmax rows sum to 1 and the reference einsum contracts the softmax axis]
//   x: [131072, 256] f32,  W: [256, 512] f32,  out: [131072, 512] f32
// R13: consolidation of the two measured-positive interventions:
//   - R12 warp-role specialization (warps 0-3 load+MMA, warps 4-7 MMA-only)
//   - R10 persistent CTAs + cross-tile prefetch (epilogue overlaps next tile)
//   - NEW: __ldcs on x (read-once) and __stcs on out (write-once) so the
//     L2 keeps the 512KB B weight images resident.
// fp16 mma.sync, 64x64 warp tiles, BM=64, KC=64 double-buffered, NT=256.
// ============================================================================

static constexpr int K_DIM  = 256;
static constexpr int N_DIM  = 512;
static constexpr int BM     = 64;
static constexpr int KC     = 64;
static constexpr int NCH    = K_DIM / KC;   // 4
static constexpr int NTILES = 131072 / BM;  // 2048
static constexpr int NT     = 256;          // 8 warps; warp = 64 rows x 64 cols
static constexpr int GRID   = 148;

// SMEM layout (bytes)
static constexpr int SM_B  = 0;            // 2 stages x 64 KB
static constexpr int SM_A  = 131072;       // 2 stages x 8 KB
static constexpr int SM_GB = 147456;       // gamma/beta f32 = 4 KB
static constexpr int SM_PS = 151552;       // psum[64][8]+psq[64][8]+stats[64][2]
static constexpr int SMEM_TOTAL = 156160;

// Pre-swizzled fp16 B chunk images: off(n,kk) = swz(n*128 + kk*2), kk = k%64.
__device__ __align__(16) unsigned char g_Bimg[NCH][65536];

// ---------------------------------------------------------------------------
__device__ __forceinline__ uint32_t smem_u32(const void* p) {
    uint32_t r;
    asm("{ .reg .u64 t; cvta.to.shared.u64 t, %1; cvt.u32.u64 %0, t; }" : "=r"(r) : "l"(p));
    return r;
}
__host__ __device__ __forceinline__ uint32_t swz(uint32_t o) { return o ^ ((o >> 3) & 0x70); }

__device__ __forceinline__ void cp16(uint32_t d, const void* s) {
    asm volatile("cp.async.cg.shared.global [%0], [%1], 16;" :: "r"(d), "l"(s));
}
__device__ __forceinline__ void cp_commit() { asm volatile("cp.async.commit_group;"); }
__device__ __forceinline__ void cp_wait0()  { asm volatile("cp.async.wait_group 0;"); }

__device__ __forceinline__ float4 ldcs4(const float* p) {
    float4 v;
    asm volatile("ld.global.cs.v4.f32 {%0,%1,%2,%3}, [%4];"
                 : "=f"(v.x), "=f"(v.y), "=f"(v.z), "=f"(v.w) : "l"(p));
    return v;
}
__device__ __forceinline__ void stcs2(float* p, float a, float b) {
    asm volatile("st.global.cs.v2.f32 [%0], {%1,%2};" :: "l"(p), "f"(a), "f"(b) : "memory");
}

__device__ __forceinline__ void ldsm4(uint32_t* r, uint32_t a) {
    asm volatile("ldmatrix.sync.aligned.m8n8.x4.shared.b16 {%0,%1,%2,%3}, [%4];"
                 : "=r"(r[0]), "=r"(r[1]), "=r"(r[2]), "=r"(r[3]) : "r"(a));
}
__device__ __forceinline__ void hmma(float* c, const uint32_t* a, const uint32_t* b) {
    asm volatile("mma.sync.aligned.m16n8k16.row.col.f32.f16.f16.f32 "
                 "{%0,%1,%2,%3},{%4,%5,%6,%7},{%8,%9},{%0,%1,%2,%3};"
                 : "+f"(c[0]), "+f"(c[1]), "+f"(c[2]), "+f"(c[3])
                 : "r"(a[0]), "r"(a[1]), "r"(a[2]), "r"(a[3]), "r"(b[0]), "r"(b[1]));
}

// ---------------------------------------------------------------------------
// Prep: W_c = m*W_v + (1-m)*W_r -> fp16, pre-swizzled chunk images.
// ---------------------------------------------------------------------------
__global__ void prep_kernel(const float* __restrict__ Wv, const float* __restrict__ Wr,
                            const float* __restrict__ mix) {
    int gid = blockIdx.x * blockDim.x + threadIdx.x;
    if (gid >= K_DIM * N_DIM) return;
    int n = gid & 511;
    int k = gid >> 9;
    float m = 1.0f / (1.0f + expf(-mix[0]));
    float w = m * Wv[k * N_DIM + n] + (1.0f - m) * Wr[k * N_DIM + n];
    int c  = k >> 6;
    int kk = k & 63;
    uint32_t off = swz((uint32_t)(n * 128 + kk * 2));
    *(__half*)(&g_Bimg[c][off]) = __float2half(w);
}

// ---------------------------------------------------------------------------
// Persistent fused GEMM (fp16 mma.sync, warp-specialized) + relu + LayerNorm
// ---------------------------------------------------------------------------
__global__ void __launch_bounds__(NT, 1)
gemm_ln_kernel(const float* __restrict__ x, const float* __restrict__ gamma,
               const float* __restrict__ beta, float* __restrict__ out) {
    extern __shared__ char smem[];
    const uint32_t sb = smem_u32(smem);
    const int tid  = threadIdx.x;
    const int wn   = tid >> 5;    // warp 0..7 -> 64-col slice, all 64 rows
    const int lane = tid & 31;
    const bool loader = (wn < 4); // one loader warp per SMSP
    const int bid  = blockIdx.x;

    // gamma/beta into smem (once)
    {
        float* gsh = (float*)(smem + SM_GB);
        for (int i = tid; i < N_DIM; i += NT) {
            gsh[i]         = gamma[i];
            gsh[N_DIM + i] = beta[i];
        }
    }

    // ldmatrix base offsets
    const uint32_t arow = (uint32_t)((lane & 15) * 128 + (lane >> 4) * 16);
    const uint32_t brow = (uint32_t)((wn * 64 + ((lane >> 4) & 1) * 8 + (lane & 7)) * 128
                                     + ((lane >> 3) & 1) * 16);

    // Loader A indexing: 1024 float4 per chunk over 128 loader threads -> 8 each
    int arowi[8], asegi[8];
    uint32_t asoff[8];
    #pragma unroll
    for (int i = 0; i < 8; i++) {
        int idx = tid + i * 128;
        arowi[i] = idx >> 4;
        asegi[i] = (idx & 15) * 4;
        asoff[i] = swz((uint32_t)((idx >> 4) * 128 + (idx & 15) * 8));
    }

    float* psum  = (float*)(smem + SM_PS);
    float* psq   = psum + 512;
    float* stats = psq + 512;
    const float* gsh = (const float*)(smem + SM_GB);
    const float* bsh = gsh + N_DIM;

    float4 av[8];
    // ---- one-time prologue (loader warps): B0 cp.async; A(tile0,c0) STS; c1 LDG ----
    if (loader) {
        #pragma unroll
        for (int i = 0; i < 32; i++) {
            int j = tid + i * 128;
            cp16(sb + SM_B + j * 16, &g_Bimg[0][j * 16]);
        }
        cp_commit();
        const size_t mb = (size_t)bid * BM;
        #pragma unroll
        for (int i = 0; i < 8; i++)
            av[i] = ldcs4(x + (mb + arowi[i]) * K_DIM + asegi[i]);
        #pragma unroll
        for (int i = 0; i < 8; i++) {
            __half2 h01 = __floats2half2_rn(av[i].x, av[i].y);
            __half2 h23 = __floats2half2_rn(av[i].z, av[i].w);
            *(uint2*)(smem + SM_A + asoff[i]) = make_uint2(*(uint32_t*)&h01, *(uint32_t*)&h23);
        }
        #pragma unroll
        for (int i = 0; i < 8; i++)
            av[i] = ldcs4(x + (mb + arowi[i]) * K_DIM + KC + asegi[i]);
    }

    for (int t = bid; t < NTILES; t += GRID) {
        const size_t m0 = (size_t)t * BM;
        const bool last_tile = (t + GRID >= NTILES);

        float acc[4][8][4];
        #pragma unroll
        for (int mt = 0; mt < 4; mt++)
            #pragma unroll
            for (int nt = 0; nt < 8; nt++)
                #pragma unroll
                for (int i = 0; i < 4; i++) acc[mt][nt][i] = 0.0f;

        #pragma unroll
        for (int c = 0; c < NCH; c++) {
            const int buf  = c & 1;
            const int nbuf = buf ^ 1;
            const bool has_next = !(last_tile && c == NCH - 1);

            if (loader) cp_wait0();
            __syncthreads();               // publish stage c; orders chunk c-2 reads

            // loader warps: produce next stage (this tile c+1, or next tile c0)
            if (loader && has_next) {
                #pragma unroll
                for (int i = 0; i < 8; i++) {
                    __half2 h01 = __floats2half2_rn(av[i].x, av[i].y);
                    __half2 h23 = __floats2half2_rn(av[i].z, av[i].w);
                    *(uint2*)(smem + SM_A + nbuf * 8192 + asoff[i]) =
                        make_uint2(*(uint32_t*)&h01, *(uint32_t*)&h23);
                }
                // LDG A two chunks ahead: (t, c+2) or (t+GRID, c-2)
                if (c < NCH - 2) {
                    #pragma unroll
                    for (int i = 0; i < 8; i++)
                        av[i] = ldcs4(x + (m0 + arowi[i]) * K_DIM + (c + 2) * KC + asegi[i]);
                } else if (!last_tile) {
                    const size_t mn = (size_t)(t + GRID) * BM;
                    #pragma unroll
                    for (int i = 0; i < 8; i++)
                        av[i] = ldcs4(x + (mn + arowi[i]) * K_DIM + (c - 2) * KC + asegi[i]);
                }
                // B next chunk image ((c+1) mod NCH)
                const unsigned char* bimg = &g_Bimg[(c + 1) & 3][0];
                #pragma unroll
                for (int i = 0; i < 32; i++) {
                    int j = tid + i * 128;
                    cp16(sb + SM_B + nbuf * 65536 + j * 16, bimg + j * 16);
                }
                cp_commit();
            }

            // ---- MMA chunk c (all warps; MMA-only warps start immediately) ----
            const uint32_t Ab = sb + SM_A + buf * 8192;
            const uint32_t Bb = sb + SM_B + buf * 65536;
            uint32_t af[2][4][4];
            #pragma unroll
            for (int mt = 0; mt < 4; mt++)
                ldsm4(af[0][mt], Ab + swz(arow + mt * 2048));
            #pragma unroll
            for (int ks = 0; ks < 4; ks++) {
                const int cur = ks & 1, nxt = cur ^ 1;
                if (ks < 3)
                    #pragma unroll
                    for (int mt = 0; mt < 4; mt++)
                        ldsm4(af[nxt][mt], Ab + swz(arow + mt * 2048 + (ks + 1) * 32));
                #pragma unroll
                for (int bt = 0; bt < 4; bt++) {
                    uint32_t bh[4];
                    ldsm4(bh, Bb + swz(brow + bt * 2048 + ks * 32));
                    #pragma unroll
                    for (int mt = 0; mt < 4; mt++) {
                        hmma(acc[mt][2 * bt],     af[cur][mt], &bh[0]);
                        hmma(acc[mt][2 * bt + 1], af[cur][mt], &bh[2]);
                    }
                }
            }
        }

        // ---------------- Epilogue: relu + LayerNorm(512) ----------------
        // (next tile's B chunk0 + A chunk0 already in flight / in smem)
        #pragma unroll
        for (int mt = 0; mt < 4; mt++) {
            #pragma unroll
            for (int half = 0; half < 2; half++) {
                float s = 0.0f, q = 0.0f;
                #pragma unroll
                for (int nt = 0; nt < 8; nt++) {
                    float v0 = fmaxf(acc[mt][nt][half * 2 + 0], 0.0f);
                    float v1 = fmaxf(acc[mt][nt][half * 2 + 1], 0.0f);
                    s += v0 + v1;
                    q = fmaf(v0, v0, q);
                    q = fmaf(v1, v1, q);
                }
                s += __shfl_xor_sync(0xFFFFFFFFu, s, 1);
                q += __shfl_xor_sync(0xFFFFFFFFu, q, 1);
                s += __shfl_xor_sync(0xFFFFFFFFu, s, 2);
                q += __shfl_xor_sync(0xFFFFFFFFu, q, 2);
                if ((lane & 3) == 0) {
                    int r = mt * 16 + (lane >> 2) + half * 8;
                    psum[r * 8 + wn] = s;
                    psq[r * 8 + wn]  = q;
                }
            }
        }
        __syncthreads();
        if (tid < BM) {
            float st = 0.0f, qt = 0.0f;
            #pragma unroll
            for (int i = 0; i < 8; i++) { st += psum[tid * 8 + i]; qt += psq[tid * 8 + i]; }
            float mean = st * (1.0f / 512.0f);
            float var  = qt * (1.0f / 512.0f) - mean * mean;
            stats[tid * 2]     = mean;
            stats[tid * 2 + 1] = rsqrtf(var + 1e-5f);
        }
        __syncthreads();

        #pragma unroll
        for (int mt = 0; mt < 4; mt++) {
            #pragma unroll
            for (int half = 0; half < 2; half++) {
                int r = mt * 16 + (lane >> 2) + half * 8;
                float mean = stats[r * 2];
                float rstd = stats[r * 2 + 1];
                float* orow = out + (size_t)(m0 + r) * N_DIM;
                #pragma unroll
                for (int nt = 0; nt < 8; nt++) {
                    int col = wn * 64 + nt * 8 + (lane & 3) * 2;
                    float ox = (fmaxf(acc[mt][nt][half * 2 + 0], 0.0f) - mean) * rstd * gsh[col]     + bsh[col];
                    float oy = (fmaxf(acc[mt][nt][half * 2 + 1], 0.0f) - mean) * rstd * gsh[col + 1] + bsh[col + 1];
                    stcs2(orow + col, ox, oy);
                }
            }
        }
        __syncthreads();   // psum/stats reuse next tile
    }
}

// ---------------------------------------------------------------------------
// Host launcher. Inputs: x, W_q, W_k, W_v, W_r, mix, gamma, beta
// ---------------------------------------------------------------------------
extern "C" void kernel_launch(void* const* d_in, const int* in_sizes, int n_in,
                              void* d_out, int out_size) {
    const float* x     = (const float*)d_in[0];
    const float* Wv    = (const float*)d_in[3];
    const float* Wr    = (const float*)d_in[4];
    const float* mix   = (const float*)d_in[5];
    const float* gamma = (const float*)d_in[6];
    const float* beta  = (const float*)d_in[7];
    float* out = (float*)d_out;

    cudaFuncSetAttribute(gemm_ln_kernel, cudaFuncAttributeMaxDynamicSharedMemorySize, SMEM_TOTAL);

    prep_kernel<<<(K_DIM * N_DIM + 255) / 256, 256>>>(Wv, Wr, mix);
    gemm_ln_kernel<<<GRID, NT, SMEM_TOTAL>>>(x, gamma, beta, out);
}